// round 12
// baseline (speedup 1.0000x reference)
#include <cuda_runtime.h>
#include <cuda_fp16.h>

#define B 2
#define S 4096
#define DIM 512
#define H 8
#define HD 64

static constexpr float EPS = 1e-5f;
static constexpr float QSCALE = 0.125f * 1.4426950408889634f;   // SCALE*LOG2E

// Scratch (__device__ globals per allocation-free rule) — fp16 activations
__device__ __half g_xn[B * S * DIM];
__device__ __half g_q[B * S * DIM];       // carries SCALE*LOG2E
__device__ __half g_k[B * S * DIM];
__device__ __half g_v[B * S * DIM];       // V TRANSPOSED [b][h][d][s], keys permuted within 16
__device__ __half g_att[B * S * DIM];
__device__ __half g_wqkv[3 * DIM * DIM];  // stacked: rows 0-511 wq, 512-1023 wk, 1024-1535 wv
__device__ __half g_wfc[DIM * DIM];

// ---------------------------------------------------------------------------
// helpers
// ---------------------------------------------------------------------------
__device__ __forceinline__ unsigned pack2h(float lo, float hi) {
    unsigned r;
    asm("cvt.rn.f16x2.f32 %0, %1, %2;" : "=r"(r) : "f"(hi), "f"(lo));
    return r;
}
__device__ __forceinline__ unsigned h2exp2(unsigned x) {
    unsigned r;
    asm("ex2.approx.f16x2 %0, %1;" : "=r"(r) : "r"(x));
    return r;
}
__device__ __forceinline__ unsigned hadd2(unsigned a, unsigned b) {
    unsigned r;
    asm("add.f16x2 %0, %1, %2;" : "=r"(r) : "r"(a), "r"(b));
    return r;
}
__device__ __forceinline__ void mmah(float* c, const unsigned* a, const unsigned* b) {
    asm volatile(
        "mma.sync.aligned.m16n8k16.row.col.f32.f16.f16.f32 "
        "{%0,%1,%2,%3},{%4,%5,%6,%7},{%8,%9},{%0,%1,%2,%3};"
        : "+f"(c[0]), "+f"(c[1]), "+f"(c[2]), "+f"(c[3])
        : "r"(a[0]), "r"(a[1]), "r"(a[2]), "r"(a[3]), "r"(b[0]), "r"(b[1]));
}
__device__ __forceinline__ void cpa16(void* dst, const void* src) {
    unsigned d = (unsigned)__cvta_generic_to_shared(dst);
    asm volatile("cp.async.cg.shared.global [%0], [%1], 16;" :: "r"(d), "l"(src));
}
#define CP_COMMIT asm volatile("cp.async.commit_group;")
#define CP_WAIT1  asm volatile("cp.async.wait_group 1;")

// within-16 key permutation used for V^T storage: r=8h+2p+b -> r'=4p+2h+b
__device__ __forceinline__ int kperm(int r) {
    return ((r >> 1) & 3) * 4 + ((r >> 3) & 1) * 2 + (r & 1);
}

// ---------------------------------------------------------------------------
// Fused LayerNorm (blocks 0..B*S-1) + weight fp16 conversion (tail blocks)
// ---------------------------------------------------------------------------
__global__ __launch_bounds__(128) void ln_prep(const float* __restrict__ x,
                                               const float* __restrict__ gamma,
                                               const float* __restrict__ beta,
                                               const float* __restrict__ wq,
                                               const float* __restrict__ wk,
                                               const float* __restrict__ wv,
                                               const float* __restrict__ wfc) {
    if (blockIdx.x >= B * S) {
        int base = (blockIdx.x - B * S) * 128 + threadIdx.x;
#pragma unroll
        for (int rep = 0; rep < 2; rep++) {
            int i = base + rep * 32768;           // float4 index < DIM*DIM/4
            float4 va = ((const float4*)wq)[i];
            float4 vb = ((const float4*)wk)[i];
            float4 vc = ((const float4*)wv)[i];
            float4 vd = ((const float4*)wfc)[i];
            __half2* q2 = (__half2*)g_wqkv;
            q2[2 * i]                         = __floats2half2_rn(va.x, va.y);
            q2[2 * i + 1]                     = __floats2half2_rn(va.z, va.w);
            q2[2 * (i + 65536)]               = __floats2half2_rn(vb.x, vb.y);
            q2[2 * (i + 65536) + 1]           = __floats2half2_rn(vb.z, vb.w);
            q2[2 * (i + 131072)]              = __floats2half2_rn(vc.x, vc.y);
            q2[2 * (i + 131072) + 1]          = __floats2half2_rn(vc.z, vc.w);
            ((__half2*)g_wfc)[2 * i]          = __floats2half2_rn(vd.x, vd.y);
            ((__half2*)g_wfc)[2 * i + 1]      = __floats2half2_rn(vd.z, vd.w);
        }
        return;
    }
    int row = blockIdx.x;
    int t = threadIdx.x;
    float4 v = ((const float4*)(x + (size_t)row * DIM))[t];
    float s  = v.x + v.y + v.z + v.w;
    float ss = v.x * v.x + v.y * v.y + v.z * v.z + v.w * v.w;
#pragma unroll
    for (int o = 16; o > 0; o >>= 1) {
        s  += __shfl_xor_sync(0xffffffff, s, o);
        ss += __shfl_xor_sync(0xffffffff, ss, o);
    }
    __shared__ float sh_s[4], sh_ss[4];
    int w = t >> 5;
    if ((t & 31) == 0) { sh_s[w] = s; sh_ss[w] = ss; }
    __syncthreads();
    s  = sh_s[0] + sh_s[1] + sh_s[2] + sh_s[3];
    ss = sh_ss[0] + sh_ss[1] + sh_ss[2] + sh_ss[3];
    float mean = s * (1.0f / DIM);
    float var  = ss * (1.0f / DIM) - mean * mean;
    float inv  = rsqrtf(var + EPS);
    float4 g  = ((const float4*)gamma)[t];
    float4 bb = ((const float4*)beta)[t];
    __half2* dst = (__half2*)(g_xn + (size_t)row * DIM);
    dst[2 * t]     = __floats2half2_rn((v.x - mean) * inv * g.x + bb.x,
                                       (v.y - mean) * inv * g.y + bb.y);
    dst[2 * t + 1] = __floats2half2_rn((v.z - mean) * inv * g.z + bb.z,
                                       (v.w - mean) * inv * g.w + bb.w);
}

// ---------------------------------------------------------------------------
// Shared GEMM mainloop (128x128 tile, BK=64, 2-stage cp.async). Stride 80.
// ---------------------------------------------------------------------------
#define GST 80
#define TTS 136

#define GEMM_MAINLOOP(APTR, WPTR)                                                        \
    float acc[4][4][4] = {};                                                             \
    _Pragma("unroll")                                                                    \
    for (int pf = 0; pf < 2; pf++) {                                                     \
        _Pragma("unroll")                                                                \
        for (int i = 0; i < 4; i++) {                                                    \
            cpa16(&As[pf][lrow[i]][lch[i]], (APTR) + (size_t)lrow[i] * DIM + 64 * pf + lch[i]); \
            cpa16(&Ws[pf][lrow[i]][lch[i]], (WPTR) + (size_t)lrow[i] * DIM + 64 * pf + lch[i]); \
        }                                                                                \
        CP_COMMIT;                                                                       \
    }                                                                                    \
    for (int kt = 0; kt < DIM / 64; kt++) {                                              \
        int buf = kt & 1;                                                                \
        CP_WAIT1;                                                                        \
        __syncthreads();                                                                 \
        _Pragma("unroll")                                                                \
        for (int ks = 0; ks < 4; ks++) {                                                 \
            unsigned af[4][4];                                                           \
            _Pragma("unroll")                                                            \
            for (int mf = 0; mf < 4; mf++) {                                             \
                uint2 lo = *(const uint2*)&As[buf][wm * 64 + mf * 16 + g][ks * 16 + 4 * tg];      \
                uint2 hi = *(const uint2*)&As[buf][wm * 64 + mf * 16 + g + 8][ks * 16 + 4 * tg];  \
                af[mf][0] = lo.x; af[mf][1] = hi.x; af[mf][2] = lo.y; af[mf][3] = hi.y;  \
            }                                                                            \
            _Pragma("unroll")                                                            \
            for (int nf = 0; nf < 4; nf++) {                                             \
                uint2 bv = *(const uint2*)&Ws[buf][wn * 32 + nf * 8 + g][ks * 16 + 4 * tg];       \
                unsigned bf[2] = {bv.x, bv.y};                                           \
                _Pragma("unroll")                                                        \
                for (int mf = 0; mf < 4; mf++)                                           \
                    mmah(acc[mf][nf], af[mf], bf);                                       \
            }                                                                            \
        }                                                                                \
        __syncthreads();                                                                 \
        if (kt + 2 < DIM / 64) {                                                         \
            _Pragma("unroll")                                                            \
            for (int i = 0; i < 4; i++) {                                                \
                cpa16(&As[buf][lrow[i]][lch[i]], (APTR) + (size_t)lrow[i] * DIM + (kt + 2) * 64 + lch[i]); \
                cpa16(&Ws[buf][lrow[i]][lch[i]], (WPTR) + (size_t)lrow[i] * DIM + (kt + 2) * 64 + lch[i]); \
            }                                                                            \
        }                                                                                \
        CP_COMMIT;                                                                       \
    }

// ---------------------------------------------------------------------------
// Fused QKV GEMM: grid (12, 64). n0: 0-511 Q, 512-1023 K, 1024+ V.
// ---------------------------------------------------------------------------
__global__ __launch_bounds__(256, 2) void qkv_gemm() {
    __shared__ __half As[2][128][GST];
    __shared__ __half Ws[2][128][GST];
    int tid = threadIdx.x, lane = tid & 31, w = tid >> 5;
    int wm = w >> 2, wn = w & 3;
    int g = lane >> 2, tg = lane & 3;
    int m0 = blockIdx.y * 128, n0 = blockIdx.x * 128;

    int lrow[4], lch[4];
#pragma unroll
    for (int i = 0; i < 4; i++) {
        int idx = tid + 256 * i;
        lrow[i] = idx >> 3;
        lch[i] = (idx & 7) * 8;
    }
    const __half* Ap = g_xn + (size_t)m0 * DIM;
    const __half* Wp = g_wqkv + (size_t)n0 * DIM;

    GEMM_MAINLOOP(Ap, Wp)

    int nmat = n0 >> 9;
    int ncol = n0 & 511;
    if (nmat < 2) {
        __half* Ch = nmat == 0 ? g_q : g_k;
        float sc = nmat == 0 ? QSCALE : 1.0f;
#pragma unroll
        for (int mf = 0; mf < 4; mf++) {
            int mrow = m0 + wm * 64 + mf * 16 + g;
#pragma unroll
            for (int nf = 0; nf < 4; nf++) {
                int col = ncol + wn * 32 + nf * 8 + 2 * tg;
                *(__half2*)(Ch + (size_t)mrow * DIM + col) =
                    __floats2half2_rn(acc[mf][nf][0] * sc, acc[mf][nf][1] * sc);
                *(__half2*)(Ch + (size_t)(mrow + 8) * DIM + col) =
                    __floats2half2_rn(acc[mf][nf][2] * sc, acc[mf][nf][3] * sc);
            }
        }
    } else {
        // V: stage transpose in smem with within-16 token permutation, then
        // coalesced STG.128 rows to [b][h][d][s]
        __half* T = &As[0][0][0];
        __syncthreads();
#pragma unroll
        for (int mf = 0; mf < 4; mf++) {
            int tokbase = wm * 64 + mf * 16;
            int t0 = tokbase + kperm(g);
            int t1 = tokbase + kperm(g + 8);
#pragma unroll
            for (int nf = 0; nf < 4; nf++) {
                int c = wn * 32 + nf * 8 + 2 * tg;
                T[(size_t)c * TTS + t0]       = __float2half(acc[mf][nf][0]);
                T[(size_t)(c + 1) * TTS + t0] = __float2half(acc[mf][nf][1]);
                T[(size_t)c * TTS + t1]       = __float2half(acc[mf][nf][2]);
                T[(size_t)(c + 1) * TTS + t1] = __float2half(acc[mf][nf][3]);
            }
        }
        __syncthreads();
        int bb = m0 >> 12, s0 = m0 & (S - 1);
#pragma unroll
        for (int i = 0; i < 8; i++) {
            int idx = tid + 256 * i;
            int c = idx >> 4, ch = (idx & 15) * 8;
            int head = (ncol + c) >> 6, d = (ncol + c) & 63;
            *(uint4*)(g_v + ((size_t)(bb * H + head) * HD + d) * S + s0 + ch) =
                *(const uint4*)&T[(size_t)c * TTS + ch];
        }
    }
}

// ---------------------------------------------------------------------------
// Final projection GEMM: out[M,512] = att @ wfc^T, fp32 out.
// ---------------------------------------------------------------------------
__global__ __launch_bounds__(256, 2) void gemm_fc(float* __restrict__ Cf) {
    __shared__ __half As[2][128][GST];
    __shared__ __half Ws[2][128][GST];
    int tid = threadIdx.x, lane = tid & 31, w = tid >> 5;
    int wm = w >> 2, wn = w & 3;
    int g = lane >> 2, tg = lane & 3;
    int m0 = blockIdx.y * 128, n0 = blockIdx.x * 128;

    int lrow[4], lch[4];
#pragma unroll
    for (int i = 0; i < 4; i++) {
        int idx = tid + 256 * i;
        lrow[i] = idx >> 3;
        lch[i] = (idx & 7) * 8;
    }
    const __half* Ap = g_att + (size_t)m0 * DIM;
    const __half* Wp = g_wfc + (size_t)n0 * DIM;

    GEMM_MAINLOOP(Ap, Wp)

#pragma unroll
    for (int mf = 0; mf < 4; mf++) {
        int mrow = m0 + wm * 64 + mf * 16 + g;
#pragma unroll
        for (int nf = 0; nf < 4; nf++) {
            int col = n0 + wn * 32 + nf * 8 + 2 * tg;
            *(float2*)(Cf + (size_t)mrow * DIM + col) =
                make_float2(acc[mf][nf][0], acc[mf][nf][1]);
            *(float2*)(Cf + (size_t)(mrow + 8) * DIM + col) =
                make_float2(acc[mf][nf][2], acc[mf][nf][3]);
        }
    }
}

// ---------------------------------------------------------------------------
// fp16 tensor-core flash attention. 512-thread CTA = 16 warps = 256 queries
// of one (b,h). No-max softmax; row sums now via HADD2 tree on the packed
// fp16 P-frags (fma pipe) instead of ones-mma — removes the serial Lacc
// tensor chain and ~11% of tensor instructions. 3-stage cp.async ring,
// one __syncthreads per tile. K/V^T stride 80 (conflict-free LDS.64).
// ---------------------------------------------------------------------------
#define KST 80
#define VST 80
#define NSTG 3

__global__ __launch_bounds__(512, 1) void attn_h() {
    __shared__ __half Kt[NSTG][64][KST];
    __shared__ __half Vt[NSTG][64][VST];

    int tid = threadIdx.x, lane = tid & 31, w = tid >> 5;   // w: 0..15
    int g = lane >> 2, tg = lane & 3;
    int b = blockIdx.z, h = blockIdx.y;
    int q0 = blockIdx.x * 256;

    const __half* qb = g_q + ((size_t)(b * S + q0 + w * 16)) * DIM + h * HD;
    unsigned qa[4][4];
#pragma unroll
    for (int ks = 0; ks < 4; ks++) {
        uint2 lo = *(const uint2*)(qb + (size_t)g * DIM + ks * 16 + 4 * tg);
        uint2 hi = *(const uint2*)(qb + (size_t)(g + 8) * DIM + ks * 16 + 4 * tg);
        qa[ks][0] = lo.x; qa[ks][1] = hi.x; qa[ks][2] = lo.y; qa[ks][3] = hi.y;
    }

    const __half* ksrc  = g_k + ((size_t)b * S) * DIM + h * HD;
    const __half* vtsrc = g_v + ((size_t)(b * H + h)) * (size_t)HD * S;

    int lrow = tid >> 3;
    int lch  = (tid & 7) * 8;

#pragma unroll
    for (int pf = 0; pf < 2; pf++) {
        cpa16(&Kt[pf][lrow][lch], ksrc + (size_t)(pf * 64 + lrow) * DIM + lch);
        cpa16(&Vt[pf][lrow][lch], vtsrc + (size_t)lrow * S + pf * 64 + lch);
        CP_COMMIT;
    }

    float O[8][4] = {};
    float l0 = 0.f, l1 = 0.f;   // per-thread partial row sums (this thread's cols)

    for (int kt = 0; kt < S / 64; kt++) {
        int buf = kt % NSTG;
        CP_WAIT1;
        __syncthreads();

        if (kt + 2 < S / 64) {
            int pbuf = (kt + 2) % NSTG;
            cpa16(&Kt[pbuf][lrow][lch], ksrc + (size_t)((kt + 2) * 64 + lrow) * DIM + lch);
            cpa16(&Vt[pbuf][lrow][lch], vtsrc + (size_t)lrow * S + (kt + 2) * 64 + lch);
            CP_COMMIT;
        }

#pragma unroll
        for (int blk = 0; blk < 2; blk++) {
            // ---- S = Q K^T for this block of 4 key-groups (16 mma) ----
            float Sc[4][4] = {};
#pragma unroll
            for (int ks = 0; ks < 4; ks++) {
#pragma unroll
                for (int q = 0; q < 4; q++) {
                    int nt = blk * 4 + q;
                    uint2 bv = *(const uint2*)&Kt[buf][nt * 8 + g][ks * 16 + 4 * tg];
                    unsigned bf[2] = {bv.x, bv.y};
                    mmah(Sc[q], qa[ks], bf);
                }
            }

            // ---- P = 2^S (fp16 pairs); result IS the PV A-frag ----
            unsigned pa[2][4];
#pragma unroll
            for (int p = 0; p < 2; p++) {
                pa[p][0] = h2exp2(pack2h(Sc[2 * p][0],     Sc[2 * p][1]));
                pa[p][1] = h2exp2(pack2h(Sc[2 * p][2],     Sc[2 * p][3]));
                pa[p][2] = h2exp2(pack2h(Sc[2 * p + 1][0], Sc[2 * p + 1][1]));
                pa[p][3] = h2exp2(pack2h(Sc[2 * p + 1][2], Sc[2 * p + 1][3]));
            }

            // ---- row sums via HADD2 tree (fma pipe; no tensor serial chain)
            {
                unsigned t0 = hadd2(hadd2(pa[0][0], pa[0][2]), hadd2(pa[1][0], pa[1][2]));
                unsigned t1 = hadd2(hadd2(pa[0][1], pa[0][3]), hadd2(pa[1][1], pa[1][3]));
                float2 f0 = __half22float2(*(__half2*)&t0);
                float2 f1 = __half22float2(*(__half2*)&t1);
                l0 += f0.x + f0.y;
                l1 += f1.x + f1.y;
            }

            // ---- O += P V (16 mma) ----
#pragma unroll
            for (int p = 0; p < 2; p++) {
                int j = blk * 2 + p;
#pragma unroll
                for (int nt = 0; nt < 8; nt++) {
                    uint2 bv = *(const uint2*)&Vt[buf][nt * 8 + g][16 * j + 4 * tg];
                    unsigned bf[2] = {bv.x, bv.y};
                    mmah(O[nt], pa[p], bf);
                }
            }
        }
    }

    // ---- complete row sums across the quad (tg lanes), normalize, store ----
    l0 += __shfl_xor_sync(0xffffffff, l0, 1);
    l0 += __shfl_xor_sync(0xffffffff, l0, 2);
    l1 += __shfl_xor_sync(0xffffffff, l1, 1);
    l1 += __shfl_xor_sync(0xffffffff, l1, 2);
    float i0 = 1.f / l0, i1 = 1.f / l1;
    __half* obase = g_att + ((size_t)(b * S + q0 + w * 16)) * DIM + h * HD;
#pragma unroll
    for (int nt = 0; nt < 8; nt++) {
        int col = nt * 8 + tg * 2;
        *(__half2*)(obase + (size_t)g * DIM + col) =
            __floats2half2_rn(O[nt][0] * i0, O[nt][1] * i0);
        *(__half2*)(obase + (size_t)(g + 8) * DIM + col) =
            __floats2half2_rn(O[nt][2] * i1, O[nt][3] * i1);
    }
}

// ---------------------------------------------------------------------------
extern "C" void kernel_launch(void* const* d_in, const int* in_sizes, int n_in,
                              void* d_out, int out_size) {
    const float* x     = (const float*)d_in[0];
    const float* gamma = (const float*)d_in[1];
    const float* beta  = (const float*)d_in[2];
    const float* wq    = (const float*)d_in[3];
    const float* wk    = (const float*)d_in[4];
    const float* wv    = (const float*)d_in[5];
    const float* wfc   = (const float*)d_in[6];
    float* out = (float*)d_out;

    ln_prep<<<B * S + 256, 128>>>(x, gamma, beta, wq, wk, wv, wfc);

    qkv_gemm<<<dim3(3 * DIM / 128, (B * S) / 128), 256>>>();

    attn_h<<<dim3(S / 256, H, B), 512>>>();

    gemm_fc<<<dim3(DIM / 128, (B * S) / 128), 256>>>(out);
}

// round 13
// speedup vs baseline: 1.0618x; 1.0618x over previous
#include <cuda_runtime.h>
#include <cuda_fp16.h>

#define B 2
#define S 4096
#define DIM 512
#define H 8
#define HD 64

static constexpr float EPS = 1e-5f;
static constexpr float QSCALE = 0.125f * 1.4426950408889634f;   // SCALE*LOG2E

// Scratch (__device__ globals per allocation-free rule) — fp16 activations
__device__ __half g_xn[B * S * DIM];
__device__ __half g_q[B * S * DIM];       // carries SCALE*LOG2E
__device__ __half g_k[B * S * DIM];
__device__ __half g_v[B * S * DIM];       // V TRANSPOSED [b][h][d][s], keys permuted within 16
__device__ __half g_att[B * S * DIM];
__device__ __half g_wqkv[3 * DIM * DIM];  // stacked: rows 0-511 wq, 512-1023 wk, 1024-1535 wv
__device__ __half g_wfc[DIM * DIM];

// ---------------------------------------------------------------------------
// helpers
// ---------------------------------------------------------------------------
__device__ __forceinline__ unsigned pack2h(float lo, float hi) {
    unsigned r;
    asm("cvt.rn.f16x2.f32 %0, %1, %2;" : "=r"(r) : "f"(hi), "f"(lo));
    return r;
}
__device__ __forceinline__ unsigned h2exp2(unsigned x) {
    unsigned r;
    asm("ex2.approx.f16x2 %0, %1;" : "=r"(r) : "r"(x));
    return r;
}
__device__ __forceinline__ void mmah(float* c, const unsigned* a, const unsigned* b) {
    asm volatile(
        "mma.sync.aligned.m16n8k16.row.col.f32.f16.f16.f32 "
        "{%0,%1,%2,%3},{%4,%5,%6,%7},{%8,%9},{%0,%1,%2,%3};"
        : "+f"(c[0]), "+f"(c[1]), "+f"(c[2]), "+f"(c[3])
        : "r"(a[0]), "r"(a[1]), "r"(a[2]), "r"(a[3]), "r"(b[0]), "r"(b[1]));
}
__device__ __forceinline__ void cpa16(void* dst, const void* src) {
    unsigned d = (unsigned)__cvta_generic_to_shared(dst);
    asm volatile("cp.async.cg.shared.global [%0], [%1], 16;" :: "r"(d), "l"(src));
}
#define CP_COMMIT asm volatile("cp.async.commit_group;")
#define CP_WAIT1  asm volatile("cp.async.wait_group 1;")

// within-16 key permutation used for V^T storage: r=8h+2p+b -> r'=4p+2h+b
__device__ __forceinline__ int kperm(int r) {
    return ((r >> 1) & 3) * 4 + ((r >> 3) & 1) * 2 + (r & 1);
}

// ---------------------------------------------------------------------------
// Fused LayerNorm (blocks 0..B*S-1) + weight fp16 conversion (tail blocks)
// ---------------------------------------------------------------------------
__global__ __launch_bounds__(128) void ln_prep(const float* __restrict__ x,
                                               const float* __restrict__ gamma,
                                               const float* __restrict__ beta,
                                               const float* __restrict__ wq,
                                               const float* __restrict__ wk,
                                               const float* __restrict__ wv,
                                               const float* __restrict__ wfc) {
    if (blockIdx.x >= B * S) {
        int base = (blockIdx.x - B * S) * 128 + threadIdx.x;
#pragma unroll
        for (int rep = 0; rep < 2; rep++) {
            int i = base + rep * 32768;           // float4 index < DIM*DIM/4
            float4 va = ((const float4*)wq)[i];
            float4 vb = ((const float4*)wk)[i];
            float4 vc = ((const float4*)wv)[i];
            float4 vd = ((const float4*)wfc)[i];
            __half2* q2 = (__half2*)g_wqkv;
            q2[2 * i]                         = __floats2half2_rn(va.x, va.y);
            q2[2 * i + 1]                     = __floats2half2_rn(va.z, va.w);
            q2[2 * (i + 65536)]               = __floats2half2_rn(vb.x, vb.y);
            q2[2 * (i + 65536) + 1]           = __floats2half2_rn(vb.z, vb.w);
            q2[2 * (i + 131072)]              = __floats2half2_rn(vc.x, vc.y);
            q2[2 * (i + 131072) + 1]          = __floats2half2_rn(vc.z, vc.w);
            ((__half2*)g_wfc)[2 * i]          = __floats2half2_rn(vd.x, vd.y);
            ((__half2*)g_wfc)[2 * i + 1]      = __floats2half2_rn(vd.z, vd.w);
        }
        return;
    }
    int row = blockIdx.x;
    int t = threadIdx.x;
    float4 v = ((const float4*)(x + (size_t)row * DIM))[t];
    float s  = v.x + v.y + v.z + v.w;
    float ss = v.x * v.x + v.y * v.y + v.z * v.z + v.w * v.w;
#pragma unroll
    for (int o = 16; o > 0; o >>= 1) {
        s  += __shfl_xor_sync(0xffffffff, s, o);
        ss += __shfl_xor_sync(0xffffffff, ss, o);
    }
    __shared__ float sh_s[4], sh_ss[4];
    int w = t >> 5;
    if ((t & 31) == 0) { sh_s[w] = s; sh_ss[w] = ss; }
    __syncthreads();
    s  = sh_s[0] + sh_s[1] + sh_s[2] + sh_s[3];
    ss = sh_ss[0] + sh_ss[1] + sh_ss[2] + sh_ss[3];
    float mean = s * (1.0f / DIM);
    float var  = ss * (1.0f / DIM) - mean * mean;
    float inv  = rsqrtf(var + EPS);
    float4 g  = ((const float4*)gamma)[t];
    float4 bb = ((const float4*)beta)[t];
    __half2* dst = (__half2*)(g_xn + (size_t)row * DIM);
    dst[2 * t]     = __floats2half2_rn((v.x - mean) * inv * g.x + bb.x,
                                       (v.y - mean) * inv * g.y + bb.y);
    dst[2 * t + 1] = __floats2half2_rn((v.z - mean) * inv * g.z + bb.z,
                                       (v.w - mean) * inv * g.w + bb.w);
}

// ---------------------------------------------------------------------------
// Shared GEMM mainloop (128x128 tile, BK=64, 2-stage cp.async). Stride 80.
// ---------------------------------------------------------------------------
#define GST 80
#define TTS 136

#define GEMM_MAINLOOP(APTR, WPTR)                                                        \
    float acc[4][4][4] = {};                                                             \
    _Pragma("unroll")                                                                    \
    for (int pf = 0; pf < 2; pf++) {                                                     \
        _Pragma("unroll")                                                                \
        for (int i = 0; i < 4; i++) {                                                    \
            cpa16(&As[pf][lrow[i]][lch[i]], (APTR) + (size_t)lrow[i] * DIM + 64 * pf + lch[i]); \
            cpa16(&Ws[pf][lrow[i]][lch[i]], (WPTR) + (size_t)lrow[i] * DIM + 64 * pf + lch[i]); \
        }                                                                                \
        CP_COMMIT;                                                                       \
    }                                                                                    \
    for (int kt = 0; kt < DIM / 64; kt++) {                                              \
        int buf = kt & 1;                                                                \
        CP_WAIT1;                                                                        \
        __syncthreads();                                                                 \
        _Pragma("unroll")                                                                \
        for (int ks = 0; ks < 4; ks++) {                                                 \
            unsigned af[4][4];                                                           \
            _Pragma("unroll")                                                            \
            for (int mf = 0; mf < 4; mf++) {                                             \
                uint2 lo = *(const uint2*)&As[buf][wm * 64 + mf * 16 + g][ks * 16 + 4 * tg];      \
                uint2 hi = *(const uint2*)&As[buf][wm * 64 + mf * 16 + g + 8][ks * 16 + 4 * tg];  \
                af[mf][0] = lo.x; af[mf][1] = hi.x; af[mf][2] = lo.y; af[mf][3] = hi.y;  \
            }                                                                            \
            _Pragma("unroll")                                                            \
            for (int nf = 0; nf < 4; nf++) {                                             \
                uint2 bv = *(const uint2*)&Ws[buf][wn * 32 + nf * 8 + g][ks * 16 + 4 * tg];       \
                unsigned bf[2] = {bv.x, bv.y};                                           \
                _Pragma("unroll")                                                        \
                for (int mf = 0; mf < 4; mf++)                                           \
                    mmah(acc[mf][nf], af[mf], bf);                                       \
            }                                                                            \
        }                                                                                \
        __syncthreads();                                                                 \
        if (kt + 2 < DIM / 64) {                                                         \
            _Pragma("unroll")                                                            \
            for (int i = 0; i < 4; i++) {                                                \
                cpa16(&As[buf][lrow[i]][lch[i]], (APTR) + (size_t)lrow[i] * DIM + (kt + 2) * 64 + lch[i]); \
                cpa16(&Ws[buf][lrow[i]][lch[i]], (WPTR) + (size_t)lrow[i] * DIM + (kt + 2) * 64 + lch[i]); \
            }                                                                            \
        }                                                                                \
        CP_COMMIT;                                                                       \
    }

// ---------------------------------------------------------------------------
// Fused QKV GEMM: grid (12, 64). n0: 0-511 Q, 512-1023 K, 1024+ V.
// ---------------------------------------------------------------------------
__global__ __launch_bounds__(256, 2) void qkv_gemm() {
    __shared__ __half As[2][128][GST];
    __shared__ __half Ws[2][128][GST];
    int tid = threadIdx.x, lane = tid & 31, w = tid >> 5;
    int wm = w >> 2, wn = w & 3;
    int g = lane >> 2, tg = lane & 3;
    int m0 = blockIdx.y * 128, n0 = blockIdx.x * 128;

    int lrow[4], lch[4];
#pragma unroll
    for (int i = 0; i < 4; i++) {
        int idx = tid + 256 * i;
        lrow[i] = idx >> 3;
        lch[i] = (idx & 7) * 8;
    }
    const __half* Ap = g_xn + (size_t)m0 * DIM;
    const __half* Wp = g_wqkv + (size_t)n0 * DIM;

    GEMM_MAINLOOP(Ap, Wp)

    int nmat = n0 >> 9;
    int ncol = n0 & 511;
    if (nmat < 2) {
        __half* Ch = nmat == 0 ? g_q : g_k;
        float sc = nmat == 0 ? QSCALE : 1.0f;
#pragma unroll
        for (int mf = 0; mf < 4; mf++) {
            int mrow = m0 + wm * 64 + mf * 16 + g;
#pragma unroll
            for (int nf = 0; nf < 4; nf++) {
                int col = ncol + wn * 32 + nf * 8 + 2 * tg;
                *(__half2*)(Ch + (size_t)mrow * DIM + col) =
                    __floats2half2_rn(acc[mf][nf][0] * sc, acc[mf][nf][1] * sc);
                *(__half2*)(Ch + (size_t)(mrow + 8) * DIM + col) =
                    __floats2half2_rn(acc[mf][nf][2] * sc, acc[mf][nf][3] * sc);
            }
        }
    } else {
        // V: stage transpose in smem with within-16 token permutation, then
        // coalesced STG.128 rows to [b][h][d][s]
        __half* T = &As[0][0][0];
        __syncthreads();
#pragma unroll
        for (int mf = 0; mf < 4; mf++) {
            int tokbase = wm * 64 + mf * 16;
            int t0 = tokbase + kperm(g);
            int t1 = tokbase + kperm(g + 8);
#pragma unroll
            for (int nf = 0; nf < 4; nf++) {
                int c = wn * 32 + nf * 8 + 2 * tg;
                T[(size_t)c * TTS + t0]       = __float2half(acc[mf][nf][0]);
                T[(size_t)(c + 1) * TTS + t0] = __float2half(acc[mf][nf][1]);
                T[(size_t)c * TTS + t1]       = __float2half(acc[mf][nf][2]);
                T[(size_t)(c + 1) * TTS + t1] = __float2half(acc[mf][nf][3]);
            }
        }
        __syncthreads();
        int bb = m0 >> 12, s0 = m0 & (S - 1);
#pragma unroll
        for (int i = 0; i < 8; i++) {
            int idx = tid + 256 * i;
            int c = idx >> 4, ch = (idx & 15) * 8;
            int head = (ncol + c) >> 6, d = (ncol + c) & 63;
            *(uint4*)(g_v + ((size_t)(bb * H + head) * HD + d) * S + s0 + ch) =
                *(const uint4*)&T[(size_t)c * TTS + ch];
        }
    }
}

// ---------------------------------------------------------------------------
// Final projection GEMM: out[M,512] = att @ wfc^T, fp32 out.
// ---------------------------------------------------------------------------
__global__ __launch_bounds__(256, 2) void gemm_fc(float* __restrict__ Cf) {
    __shared__ __half As[2][128][GST];
    __shared__ __half Ws[2][128][GST];
    int tid = threadIdx.x, lane = tid & 31, w = tid >> 5;
    int wm = w >> 2, wn = w & 3;
    int g = lane >> 2, tg = lane & 3;
    int m0 = blockIdx.y * 128, n0 = blockIdx.x * 128;

    int lrow[4], lch[4];
#pragma unroll
    for (int i = 0; i < 4; i++) {
        int idx = tid + 256 * i;
        lrow[i] = idx >> 3;
        lch[i] = (idx & 7) * 8;
    }
    const __half* Ap = g_att + (size_t)m0 * DIM;
    const __half* Wp = g_wfc + (size_t)n0 * DIM;

    GEMM_MAINLOOP(Ap, Wp)

#pragma unroll
    for (int mf = 0; mf < 4; mf++) {
        int mrow = m0 + wm * 64 + mf * 16 + g;
#pragma unroll
        for (int nf = 0; nf < 4; nf++) {
            int col = n0 + wn * 32 + nf * 8 + 2 * tg;
            *(float2*)(Cf + (size_t)mrow * DIM + col) =
                make_float2(acc[mf][nf][0], acc[mf][nf][1]);
            *(float2*)(Cf + (size_t)(mrow + 8) * DIM + col) =
                make_float2(acc[mf][nf][2], acc[mf][nf][3]);
        }
    }
}

// ---------------------------------------------------------------------------
// fp16 tensor-core flash attention. 512-thread CTA = 16 warps = 256 queries
// of one (b,h). R10 math (no-max softmax, ones-mma row sums) restored.
// NOW: 128-key tiles (32 tiles instead of 64 -> half the CTA barriers,
// 2x prefetch distance), 3-stage cp.async ring in dynamic smem (~117 KB),
// UNCONDITIONAL commit per iteration (fixes latent last-tile wait race).
// K rows stride 80 halves (40 words ≡ 8 mod 32), V^T rows 128 keys at
// stride 144 halves (72 words ≡ 8) -> all LDS.64 frags conflict-free.
// ---------------------------------------------------------------------------
#define KSTW 80
#define VSTW 144
#define KSTAGE (128 * KSTW)
#define VSTAGE (64 * VSTW)
#define ATT_SMEM ((3 * KSTAGE + 3 * VSTAGE) * 2)
#define NTILE (S / 128)

__global__ __launch_bounds__(512, 1) void attn_h() {
    extern __shared__ __half sm[];
    __half* Kb = sm;                    // 3 stages of [128][KSTW]
    __half* Vb = sm + 3 * KSTAGE;       // 3 stages of [64][VSTW]

    int tid = threadIdx.x, lane = tid & 31, w = tid >> 5;   // w: 0..15
    int g = lane >> 2, tg = lane & 3;
    int b = blockIdx.z, h = blockIdx.y;
    int q0 = blockIdx.x * 256;

    // Q A-frags (8 x LDG.64)
    const __half* qb = g_q + ((size_t)(b * S + q0 + w * 16)) * DIM + h * HD;
    unsigned qa[4][4];
#pragma unroll
    for (int ks = 0; ks < 4; ks++) {
        uint2 lo = *(const uint2*)(qb + (size_t)g * DIM + ks * 16 + 4 * tg);
        uint2 hi = *(const uint2*)(qb + (size_t)(g + 8) * DIM + ks * 16 + 4 * tg);
        qa[ks][0] = lo.x; qa[ks][1] = hi.x; qa[ks][2] = lo.y; qa[ks][3] = hi.y;
    }

    const __half* ksrc  = g_k + ((size_t)b * S) * DIM + h * HD;          // [s][dim]
    const __half* vtsrc = g_v + ((size_t)(b * H + h)) * (size_t)HD * S;  // [d][s] permuted

    // per-tile loads: K = 128 rows x 8 chunks, V = 64 rows x 16 chunks;
    // 1024 chunks each, 512 threads -> 2 chunks per operand per thread
    int krow[2], kch[2], vrow[2], vch[2];
#pragma unroll
    for (int i = 0; i < 2; i++) {
        int idx = tid + 512 * i;
        krow[i] = idx >> 3;  kch[i] = (idx & 7) * 8;
        vrow[i] = idx >> 4;  vch[i] = (idx & 15) * 8;
    }

    // prologue: tiles 0,1 -> stages 0,1
#pragma unroll
    for (int pf = 0; pf < 2; pf++) {
#pragma unroll
        for (int i = 0; i < 2; i++) {
            cpa16(Kb + pf * KSTAGE + krow[i] * KSTW + kch[i],
                  ksrc + (size_t)(pf * 128 + krow[i]) * DIM + kch[i]);
            cpa16(Vb + pf * VSTAGE + vrow[i] * VSTW + vch[i],
                  vtsrc + (size_t)vrow[i] * S + pf * 128 + vch[i]);
        }
        CP_COMMIT;
    }

    float O[8][4] = {};
    float Lacc[4] = {};
    const unsigned onesb[2] = {0x3C003C00u, 0x3C003C00u};

    for (int kt = 0; kt < NTILE; kt++) {
        int stg = kt % 3;
        CP_WAIT1;           // groups: tile kt is (kt)-th group; wait leaves <=1 newest pending
        __syncthreads();    // stage (kt-1)%3 fully consumed by all warps

        if (kt + 2 < NTILE) {
            int pst = (kt + 2) % 3;
#pragma unroll
            for (int i = 0; i < 2; i++) {
                cpa16(Kb + pst * KSTAGE + krow[i] * KSTW + kch[i],
                      ksrc + (size_t)((kt + 2) * 128 + krow[i]) * DIM + kch[i]);
                cpa16(Vb + pst * VSTAGE + vrow[i] * VSTW + vch[i],
                      vtsrc + (size_t)vrow[i] * S + (kt + 2) * 128 + vch[i]);
            }
        }
        CP_COMMIT;          // UNCONDITIONAL: keeps group indexing exact through the tail

        const __half* K = Kb + stg * KSTAGE;
        const __half* V = Vb + stg * VSTAGE;

#pragma unroll
        for (int blk = 0; blk < 4; blk++) {
            // ---- S = Q K^T for 4 key-groups (16 mma) ----
            float Sc[4][4] = {};
#pragma unroll
            for (int ks = 0; ks < 4; ks++) {
#pragma unroll
                for (int q = 0; q < 4; q++) {
                    int nt = blk * 4 + q;
                    uint2 bv = *(const uint2*)&K[(nt * 8 + g) * KSTW + ks * 16 + 4 * tg];
                    unsigned bf[2] = {bv.x, bv.y};
                    mmah(Sc[q], qa[ks], bf);
                }
            }

            // ---- P = 2^S (fp16 pairs) + ones-mma row sums ----
            unsigned pa[2][4];
#pragma unroll
            for (int p = 0; p < 2; p++) {
                pa[p][0] = h2exp2(pack2h(Sc[2 * p][0],     Sc[2 * p][1]));
                pa[p][1] = h2exp2(pack2h(Sc[2 * p][2],     Sc[2 * p][3]));
                pa[p][2] = h2exp2(pack2h(Sc[2 * p + 1][0], Sc[2 * p + 1][1]));
                pa[p][3] = h2exp2(pack2h(Sc[2 * p + 1][2], Sc[2 * p + 1][3]));
                mmah(Lacc, pa[p], onesb);
            }

            // ---- O += P V (16 mma), single LDS.64 B-frags ----
#pragma unroll
            for (int p = 0; p < 2; p++) {
                int jj = blk * 2 + p;
#pragma unroll
                for (int nt = 0; nt < 8; nt++) {
                    uint2 bv = *(const uint2*)&V[(nt * 8 + g) * VSTW + 16 * jj + 4 * tg];
                    unsigned bf[2] = {bv.x, bv.y};
                    mmah(O[nt], pa[p], bf);
                }
            }
        }
    }

    // ---- normalize + store (Lacc holds exact full row sums) ----
    float i0 = 1.f / Lacc[0], i1 = 1.f / Lacc[2];
    __half* obase = g_att + ((size_t)(b * S + q0 + w * 16)) * DIM + h * HD;
#pragma unroll
    for (int nt = 0; nt < 8; nt++) {
        int col = nt * 8 + tg * 2;
        *(__half2*)(obase + (size_t)g * DIM + col) =
            __floats2half2_rn(O[nt][0] * i0, O[nt][1] * i0);
        *(__half2*)(obase + (size_t)(g + 8) * DIM + col) =
            __floats2half2_rn(O[nt][2] * i1, O[nt][3] * i1);
    }
}

// ---------------------------------------------------------------------------
extern "C" void kernel_launch(void* const* d_in, const int* in_sizes, int n_in,
                              void* d_out, int out_size) {
    const float* x     = (const float*)d_in[0];
    const float* gamma = (const float*)d_in[1];
    const float* beta  = (const float*)d_in[2];
    const float* wq    = (const float*)d_in[3];
    const float* wk    = (const float*)d_in[4];
    const float* wv    = (const float*)d_in[5];
    const float* wfc   = (const float*)d_in[6];
    float* out = (float*)d_out;

    cudaFuncSetAttribute(attn_h, cudaFuncAttributeMaxDynamicSharedMemorySize, ATT_SMEM);

    ln_prep<<<B * S + 256, 128>>>(x, gamma, beta, wq, wk, wv, wfc);

    qkv_gemm<<<dim3(3 * DIM / 128, (B * S) / 128), 256>>>();

    attn_h<<<dim3(S / 256, H, B), 512, ATT_SMEM>>>();

    gemm_fc<<<dim3(DIM / 128, (B * S) / 128), 256>>>(out);
}